// round 14
// baseline (speedup 1.0000x reference)
#include <cuda_runtime.h>
#include <cuda_fp16.h>
#include <cstdint>
#include <math.h>

#define TOKS 8192
#define DIMM 768
#define HIDM 3072
#define NSEQ 1024
#define NHEADS 12
#define HDIM 64
#define SCALEQ 0.125f

// ---------------- scratch ----------------
__device__ __align__(16) __half g_hh[TOKS*DIMM];       // LN1 out (fp16)
__device__ __align__(16) __half g_h2[TOKS*DIMM];       // LN2 out (fp16)
__device__ __align__(16) __half g_o [TOKS*DIMM];       // attention out (fp16)
__device__ __align__(16) __half g_mi[TOKS*HIDM];       // fc1+gelu out (fp16)
__device__ __align__(16) __half g_q [96*NSEQ*HDIM];
__device__ __align__(16) __half g_k [96*NSEQ*HDIM];
__device__ __align__(16) __half g_v [96*NSEQ*HDIM];
__device__ float  g_x1[TOKS*DIMM];
// converted fp16 weights, packed
#define OFF_KV 0
#define OFF_SQ 1179648
#define OFF_CQ 1720320
#define OFF_PJ 1916928
#define OFF_F1 2506752
#define OFF_F2 4866048
#define WH_TOTAL 7225344
__device__ __align__(16) __half g_wh[WH_TOTAL];

// ---------------- helpers ----------------
__device__ __forceinline__ uint32_t smem_u32(const void* p){
  uint32_t a; asm("{ .reg .u64 t; cvta.to.shared.u64 t, %1; cvt.u32.u64 %0, t; }" : "=r"(a) : "l"(p));
  return a;
}
__device__ __forceinline__ float gelu_exact(float x){
  return 0.5f * x * (1.0f + erff(x * 0.70710678118654752f));
}
__device__ __forceinline__ void mma_fp16(float c[4], const uint32_t a[4], uint32_t b0, uint32_t b1){
  asm volatile("mma.sync.aligned.m16n8k16.row.col.f32.f16.f16.f32 "
      "{%0,%1,%2,%3},{%4,%5,%6,%7},{%8,%9},{%0,%1,%2,%3};"
      : "+f"(c[0]), "+f"(c[1]), "+f"(c[2]), "+f"(c[3])
      : "r"(a[0]), "r"(a[1]), "r"(a[2]), "r"(a[3]), "r"(b0), "r"(b1));
}
__device__ __forceinline__ void ldsm4(uint32_t r[4], uint32_t a){
  asm volatile("ldmatrix.sync.aligned.m8n8.x4.shared.b16 {%0,%1,%2,%3}, [%4];"
    : "=r"(r[0]), "=r"(r[1]), "=r"(r[2]), "=r"(r[3]) : "r"(a));
}
__device__ __forceinline__ uint2 f4h4(float4 v){
  __half2 h01 = __float22half2_rn(make_float2(v.x, v.y));
  __half2 h23 = __float22half2_rn(make_float2(v.z, v.w));
  uint2 u;
  u.x = *(uint32_t*)&h01;
  u.y = *(uint32_t*)&h23;
  return u;
}

// smem tile row: 32 data halves + 8 pad = 80B stride, conflict-free ldmatrix
#define HROW 40
#define HROWB 80

// ---------------- fp16 GEMM, 128x64 tile, 128 thr, 4 CTAs/SM -------------------
// warp tile 64x32 (wm=warp>>1, wn=warp&1). double-buffered reg-prefetch.
// MODE 0: float out = acc + bias + res   MODE 1: half out = gelu(acc + bias)
template<int MODE>
__global__ __launch_bounds__(128, 4) void gemm_h(
    const __half* __restrict__ A, const __half* __restrict__ W,
    const float* __restrict__ bias, const float* __restrict__ res,
    void* __restrict__ outv, int Nc, int K){
  __shared__ __align__(16) __half As[2][128][HROW];
  __shared__ __align__(16) __half Bs[2][64][HROW];
  int tid = threadIdx.x;
  int warp = tid>>5, lane = tid&31, g = lane>>2, t = lane&3;
  int wm = warp>>1, wn = warp&1;
  int bm = blockIdx.y*128, bn = blockIdx.x*64;

  // loaders: A one thread per row (4 uint4); B two threads per row (2 uint4 each)
  const uint4* asrc = (const uint4*)(A + (size_t)(bm+tid)*K);
  int lrB = tid>>1, lgB = tid&1;
  const uint4* bsrc = (const uint4*)(W + (size_t)(bn+lrB)*K) + lgB*2;

  uint32_t sbA = smem_u32(&As[0][0][0]);
  uint32_t sbB = smem_u32(&Bs[0][0][0]);
  const uint32_t BUFA = 128*HROWB;
  const uint32_t BUFB = 64*HROWB;

  float acc[4][4][4];
  #pragma unroll
  for (int i=0;i<4;i++)
    #pragma unroll
    for (int j=0;j<4;j++){ acc[i][j][0]=0.f; acc[i][j][1]=0.f; acc[i][j][2]=0.f; acc[i][j][3]=0.f; }

  uint32_t a_off[4], b_off[2];
  {
    uint32_t arow_l = (uint32_t)(lane&15);
    uint32_t acol_l = (uint32_t)((lane>>4)*16);
    #pragma unroll
    for (int mt=0;mt<4;mt++)
      a_off[mt] = (uint32_t)(wm*64 + mt*16 + arow_l)*HROWB + acol_l;
    uint32_t brow_l = (uint32_t)(((lane>>4)*8) + (lane&7));
    uint32_t bcol_l = (uint32_t)((lane&8) ? 16 : 0);
    #pragma unroll
    for (int p=0;p<2;p++)
      b_off[p] = (uint32_t)(wn*32 + p*16 + brow_l)*HROWB + bcol_l;
  }

  // preload chunk 0
  uint4 ra0 = asrc[0], ra1 = asrc[1], ra2 = asrc[2], ra3 = asrc[3];
  uint4 rb0 = bsrc[0], rb1 = bsrc[1];
  {
    uint4* da = (uint4*)&As[0][tid][0];
    da[0]=ra0; da[1]=ra1; da[2]=ra2; da[3]=ra3;
    uint4* db = (uint4*)&Bs[0][lrB][lgB*16];
    db[0]=rb0; db[1]=rb1;
  }
  __syncthreads();

  int KT = K >> 5;
  for (int kt=0; kt<KT; kt++){
    int buf = kt & 1;
    uint32_t baseA = sbA + buf*BUFA;
    uint32_t baseB = sbB + buf*BUFB;
    if (kt+1 < KT){
      ra0 = asrc[(kt+1)*4];   ra1 = asrc[(kt+1)*4+1];
      ra2 = asrc[(kt+1)*4+2]; ra3 = asrc[(kt+1)*4+3];
      rb0 = bsrc[(kt+1)*4];   rb1 = bsrc[(kt+1)*4+1];
    }
    #pragma unroll
    for (int kk=0; kk<2; kk++){
      uint32_t kb = kk*32;
      uint32_t af[4][4], bf[2][4];
      #pragma unroll
      for (int mt=0;mt<4;mt++) ldsm4(af[mt], baseA + a_off[mt] + kb);
      #pragma unroll
      for (int p=0;p<2;p++)    ldsm4(bf[p],  baseB + b_off[p] + kb);
      #pragma unroll
      for (int mt=0;mt<4;mt++){
        mma_fp16(acc[mt][0], af[mt], bf[0][0], bf[0][1]);
        mma_fp16(acc[mt][1], af[mt], bf[0][2], bf[0][3]);
        mma_fp16(acc[mt][2], af[mt], bf[1][0], bf[1][1]);
        mma_fp16(acc[mt][3], af[mt], bf[1][2], bf[1][3]);
      }
    }
    if (kt+1 < KT){
      int nb = buf^1;
      uint4* da = (uint4*)&As[nb][tid][0];
      da[0]=ra0; da[1]=ra1; da[2]=ra2; da[3]=ra3;
      uint4* db = (uint4*)&Bs[nb][lrB][lgB*16];
      db[0]=rb0; db[1]=rb1;
    }
    __syncthreads();
  }

  #pragma unroll
  for (int mt=0;mt<4;mt++){
    int row = bm + wm*64 + mt*16 + g;
    #pragma unroll
    for (int nt=0;nt<4;nt++){
      int col = bn + wn*32 + nt*8 + 2*t;
      float b0v = bias[col], b1v = bias[col+1];
      float v00 = acc[mt][nt][0] + b0v, v01 = acc[mt][nt][1] + b1v;
      float v10 = acc[mt][nt][2] + b0v, v11 = acc[mt][nt][3] + b1v;
      if (MODE==0){
        float* out = (float*)outv;
        const float* r0 = res + (size_t)row*Nc + col;
        const float* r1 = res + (size_t)(row+8)*Nc + col;
        v00 += r0[0]; v01 += r0[1]; v10 += r1[0]; v11 += r1[1];
        *(float2*)(out + (size_t)row*Nc + col)     = make_float2(v00,v01);
        *(float2*)(out + (size_t)(row+8)*Nc + col) = make_float2(v10,v11);
      } else {
        __half* out = (__half*)outv;
        v00 = gelu_exact(v00); v01 = gelu_exact(v01);
        v10 = gelu_exact(v10); v11 = gelu_exact(v11);
        *(__half2*)(out + (size_t)row*Nc + col)     = __floats2half2_rn(v00,v01);
        *(__half2*)(out + (size_t)(row+8)*Nc + col) = __floats2half2_rn(v10,v11);
      }
    }
  }
}

// ---------------- fp16 fused QKV (128x64 tile, 128 thr): Nc=2304 ---------------
__global__ __launch_bounds__(128, 4) void qkv_h(
    const __half* __restrict__ A, const __half* __restrict__ WH,
    const float* __restrict__ kv_b, const float* __restrict__ sq_b, const float* __restrict__ cq_b,
    const int* __restrict__ cvals,
    __half* __restrict__ qo, __half* __restrict__ ko, __half* __restrict__ vo){
  __shared__ __align__(16) __half As[2][128][HROW];
  __shared__ __align__(16) __half Bs[2][64][HROW];
  const int K = DIMM;
  int tid = threadIdx.x;
  int warp = tid>>5, lane = tid&31, g = lane>>2, t = lane&3;
  int wm = warp>>1, wn = warp&1;
  int bm = blockIdx.y*128, bn = blockIdx.x*64;
  int bb = bm >> 10;
  int coh = cvals[bb];

  const uint4* asrc = (const uint4*)(A + (size_t)(bm+tid)*K);
  int lrB = tid>>1, lgB = tid&1;
  int j = bn + lrB;
  const __half* bw;
  if (j < 1536)      bw = WH + OFF_KV + (size_t)j*K;
  else if (j < 2240) bw = WH + OFF_SQ + (size_t)(j-1536)*K;
  else               bw = WH + OFF_CQ + ((size_t)coh*64 + (j-2240))*K;
  const uint4* bsrc = (const uint4*)bw + lgB*2;

  uint32_t sbA = smem_u32(&As[0][0][0]);
  uint32_t sbB = smem_u32(&Bs[0][0][0]);
  const uint32_t BUFA = 128*HROWB;
  const uint32_t BUFB = 64*HROWB;

  float acc[4][4][4];
  #pragma unroll
  for (int i=0;i<4;i++)
    #pragma unroll
    for (int jx=0;jx<4;jx++){ acc[i][jx][0]=0.f; acc[i][jx][1]=0.f; acc[i][jx][2]=0.f; acc[i][jx][3]=0.f; }

  uint32_t a_off[4], b_off[2];
  {
    uint32_t arow_l = (uint32_t)(lane&15);
    uint32_t acol_l = (uint32_t)((lane>>4)*16);
    #pragma unroll
    for (int mt=0;mt<4;mt++)
      a_off[mt] = (uint32_t)(wm*64 + mt*16 + arow_l)*HROWB + acol_l;
    uint32_t brow_l = (uint32_t)(((lane>>4)*8) + (lane&7));
    uint32_t bcol_l = (uint32_t)((lane&8) ? 16 : 0);
    #pragma unroll
    for (int p=0;p<2;p++)
      b_off[p] = (uint32_t)(wn*32 + p*16 + brow_l)*HROWB + bcol_l;
  }

  uint4 ra0 = asrc[0], ra1 = asrc[1], ra2 = asrc[2], ra3 = asrc[3];
  uint4 rb0 = bsrc[0], rb1 = bsrc[1];
  {
    uint4* da = (uint4*)&As[0][tid][0];
    da[0]=ra0; da[1]=ra1; da[2]=ra2; da[3]=ra3;
    uint4* db = (uint4*)&Bs[0][lrB][lgB*16];
    db[0]=rb0; db[1]=rb1;
  }
  __syncthreads();

  const int KT = K >> 5;  // 24
  for (int kt=0; kt<KT; kt++){
    int buf = kt & 1;
    uint32_t baseA = sbA + buf*BUFA;
    uint32_t baseB = sbB + buf*BUFB;
    if (kt+1 < KT){
      ra0 = asrc[(kt+1)*4];   ra1 = asrc[(kt+1)*4+1];
      ra2 = asrc[(kt+1)*4+2]; ra3 = asrc[(kt+1)*4+3];
      rb0 = bsrc[(kt+1)*4];   rb1 = bsrc[(kt+1)*4+1];
    }
    #pragma unroll
    for (int kk=0; kk<2; kk++){
      uint32_t kb = kk*32;
      uint32_t af[4][4], bf[2][4];
      #pragma unroll
      for (int mt=0;mt<4;mt++) ldsm4(af[mt], baseA + a_off[mt] + kb);
      #pragma unroll
      for (int p=0;p<2;p++)    ldsm4(bf[p],  baseB + b_off[p] + kb);
      #pragma unroll
      for (int mt=0;mt<4;mt++){
        mma_fp16(acc[mt][0], af[mt], bf[0][0], bf[0][1]);
        mma_fp16(acc[mt][1], af[mt], bf[0][2], bf[0][3]);
        mma_fp16(acc[mt][2], af[mt], bf[1][0], bf[1][1]);
        mma_fp16(acc[mt][3], af[mt], bf[1][2], bf[1][3]);
      }
    }
    if (kt+1 < KT){
      int nb = buf^1;
      uint4* da = (uint4*)&As[nb][tid][0];
      da[0]=ra0; da[1]=ra1; da[2]=ra2; da[3]=ra3;
      uint4* db = (uint4*)&Bs[nb][lrB][lgB*16];
      db[0]=rb0; db[1]=rb1;
    }
    __syncthreads();
  }

  // scatter epilogue into fp16 q/k/v [B*H, N, 64]
  #pragma unroll
  for (int mt=0;mt<4;mt++){
    int row = bm + wm*64 + mt*16 + g;
    int n = row & 1023;
    #pragma unroll
    for (int nt=0;nt<4;nt++){
      int col = bn + wn*32 + nt*8 + 2*t;
      float bias0, bias1;
      __half* dst;
      if (col < 1536){
        int part = (col >= 768) ? 1 : 0;
        int cc = col - part*768;
        int head = cc >> 6, hd = cc & 63;
        dst = (part ? vo : ko) + ((size_t)(bb*NHEADS + head)*NSEQ + n)*HDIM + hd;
        bias0 = kv_b[col]; bias1 = kv_b[col+1];
      } else if (col < 2240){
        int cc = col - 1536;
        int head = cc >> 6, hd = cc & 63;
        dst = qo + ((size_t)(bb*NHEADS + head)*NSEQ + n)*HDIM + hd;
        bias0 = sq_b[cc]; bias1 = sq_b[cc+1];
      } else {
        int hd = col - 2240;
        dst = qo + ((size_t)(bb*NHEADS + 11)*NSEQ + n)*HDIM + hd;
        bias0 = cq_b[coh*64 + hd]; bias1 = cq_b[coh*64 + hd + 1];
      }
      *(__half2*)dst = __floats2half2_rn(acc[mt][nt][0] + bias0, acc[mt][nt][1] + bias1);
      *(__half2*)(dst + 8*HDIM) = __floats2half2_rn(acc[mt][nt][2] + bias0, acc[mt][nt][3] + bias1);
    }
  }
}

// ---------------- f32 -> f16 weight conversion ----------------
__global__ __launch_bounds__(256) void cvt_h(const float* __restrict__ in,
                                             __half* __restrict__ out, int n4){
  int i = blockIdx.x*256 + threadIdx.x;
  if (i < n4){
    float4 v = *(const float4*)(in + (size_t)i*4);
    *(uint2*)(out + (size_t)i*4) = f4h4(v);
  }
}

// ---------------- LayerNorm (fp16 out) ----------------
__global__ __launch_bounds__(256) void ln_h(const float* __restrict__ x,
    const float* __restrict__ gam, const float* __restrict__ bet, __half* __restrict__ out){
  __shared__ float red[2][8];
  int row = blockIdx.x, tid = threadIdx.x;
  const float* xr = x + (size_t)row*DIMM;
  float v0 = xr[tid], v1 = xr[tid+256], v2 = xr[tid+512];
  float s = v0+v1+v2;
  float q = v0*v0 + v1*v1 + v2*v2;
  #pragma unroll
  for (int o=16;o;o>>=1){ s += __shfl_xor_sync(0xffffffffu, s, o); q += __shfl_xor_sync(0xffffffffu, q, o); }
  int wid = tid>>5, lane = tid&31;
  if (lane==0){ red[0][wid]=s; red[1][wid]=q; }
  __syncthreads();
  if (tid < 32){
    s = (lane<8)? red[0][lane] : 0.f;
    q = (lane<8)? red[1][lane] : 0.f;
    #pragma unroll
    for (int o=4;o;o>>=1){ s += __shfl_xor_sync(0xffffffffu, s, o); q += __shfl_xor_sync(0xffffffffu, q, o); }
    if (lane==0){ red[0][0]=s; red[1][0]=q; }
  }
  __syncthreads();
  float mu  = red[0][0] * (1.f/(float)DIMM);
  float var = red[1][0] * (1.f/(float)DIMM) - mu*mu;
  float rs = rsqrtf(var + 1e-5f);
  __half* orow = out + (size_t)row*DIMM;
  orow[tid]     = __float2half_rn((v0-mu)*rs*gam[tid]     + bet[tid]);
  orow[tid+256] = __float2half_rn((v1-mu)*rs*gam[tid+256] + bet[tid+256]);
  orow[tid+512] = __float2half_rn((v2-mu)*rs*gam[tid+512] + bet[tid+512]);
}

// ---------------- flash attention, fp16 mma + ldmatrix ----------------
#define ATT_VT 18432
#define ATT_PS 35840
#define ATT_SMEM 70656
__global__ __launch_bounds__(256, 1) void attn_h(
    const __half* __restrict__ qb, const __half* __restrict__ kb,
    const __half* __restrict__ vb, __half* __restrict__ ob){
  extern __shared__ __align__(16) char sm[];
  uint32_t sb = smem_u32(sm);
  int tid = threadIdx.x, warp = tid>>5, lane = tid&31, g = lane>>2, t = lane&3;
  int bh = blockIdx.y, qt = blockIdx.x;
  const __half* Q = qb + ((size_t)bh*NSEQ + qt*128)*HDIM;
  const __half* K = kb + (size_t)bh*NSEQ*HDIM;
  const __half* V = vb + (size_t)bh*NSEQ*HDIM;

  uint32_t arow_l = (uint32_t)(lane&15);
  uint32_t acol_l = (uint32_t)((lane>>4)*16);
  uint32_t brow_l = (uint32_t)(((lane>>4)*8) + (lane&7));
  uint32_t bcol_l = (uint32_t)((lane&8) ? 16 : 0);

  for (int i=tid; i<1024; i+=256){
    int r = i>>3, c = (i&7)*8;
    *(uint4*)(sm + r*144 + c*2) = *(const uint4*)(Q + (size_t)r*HDIM + c);
  }
  __syncthreads();
  uint32_t qa[4][4];
  #pragma unroll
  for (int kc=0;kc<4;kc++)
    ldsm4(qa[kc], sb + (uint32_t)(warp*16 + arow_l)*144 + acol_l + kc*32);
  __syncthreads();

  float m0=-1e30f, m1=-1e30f, l0=0.f, l1=0.f;
  float oa[8][4];
  #pragma unroll
  for (int dt=0;dt<8;dt++){ oa[dt][0]=0.f; oa[dt][1]=0.f; oa[dt][2]=0.f; oa[dt][3]=0.f; }

  for (int it=0; it<8; it++){
    const __half* Kt = K + (size_t)it*128*HDIM;
    const __half* Vt = V + (size_t)it*128*HDIM;
    for (int i=tid; i<1024; i+=256){
      int r = i>>3, c = (i&7)*8;
      *(uint4*)(sm + r*144 + c*2) = *(const uint4*)(Kt + (size_t)r*HDIM + c);
    }
    for (int i=tid; i<1024; i+=256){
      int key = i & 127, d8 = (i>>7)<<3;
      uint4 vv = *(const uint4*)(Vt + (size_t)key*HDIM + d8);
      const __half* hp = (const __half*)&vv;
      #pragma unroll
      for (int jj=0;jj<8;jj++)
        *(__half*)(sm + ATT_VT + (d8+jj)*272 + key*2) = hp[jj];
    }
    __syncthreads();

    float s[16][4];
    #pragma unroll
    for (int nt=0;nt<16;nt++){ s[nt][0]=0.f; s[nt][1]=0.f; s[nt][2]=0.f; s[nt][3]=0.f; }
    #pragma unroll
    for (int kc=0;kc<4;kc++){
      #pragma unroll
      for (int p=0;p<8;p++){
        uint32_t bf[4];
        ldsm4(bf, sb + (uint32_t)(p*16 + brow_l)*144 + bcol_l + kc*32);
        mma_fp16(s[2*p],   qa[kc], bf[0], bf[1]);
        mma_fp16(s[2*p+1], qa[kc], bf[2], bf[3]);
      }
    }
    #pragma unroll
    for (int nt=0;nt<16;nt++){
      s[nt][0]*=SCALEQ; s[nt][1]*=SCALEQ; s[nt][2]*=SCALEQ; s[nt][3]*=SCALEQ;
    }
    float mx0 = -1e30f, mx1 = -1e30f;
    #pragma unroll
    for (int nt=0;nt<16;nt++){
      mx0 = fmaxf(mx0, fmaxf(s[nt][0], s[nt][1]));
      mx1 = fmaxf(mx1, fmaxf(s[nt][2], s[nt][3]));
    }
    mx0 = fmaxf(mx0, __shfl_xor_sync(0xffffffffu, mx0, 1));
    mx0 = fmaxf(mx0, __shfl_xor_sync(0xffffffffu, mx0, 2));
    mx1 = fmaxf(mx1, __shfl_xor_sync(0xffffffffu, mx1, 1));
    mx1 = fmaxf(mx1, __shfl_xor_sync(0xffffffffu, mx1, 2));
    float nm0 = fmaxf(m0, mx0), nm1 = fmaxf(m1, mx1);
    float al0 = __expf(m0 - nm0), al1 = __expf(m1 - nm1);
    m0 = nm0; m1 = nm1;
    float sum0 = 0.f, sum1 = 0.f;
    #pragma unroll
    for (int nt=0;nt<16;nt++){
      s[nt][0] = __expf(s[nt][0] - m0);
      s[nt][1] = __expf(s[nt][1] - m0);
      s[nt][2] = __expf(s[nt][2] - m1);
      s[nt][3] = __expf(s[nt][3] - m1);
      sum0 += s[nt][0] + s[nt][1];
      sum1 += s[nt][2] + s[nt][3];
    }
    l0 = l0*al0 + sum0;
    l1 = l1*al1 + sum1;
    #pragma unroll
    for (int dt=0;dt<8;dt++){
      oa[dt][0]*=al0; oa[dt][1]*=al0; oa[dt][2]*=al1; oa[dt][3]*=al1;
    }
    {
      char* psw = sm + ATT_PS + warp*4352;
      #pragma unroll
      for (int nt=0;nt<16;nt++){
        *(__half2*)(psw + g*272     + (nt*8 + 2*t)*2) = __floats2half2_rn(s[nt][0], s[nt][1]);
        *(__half2*)(psw + (g+8)*272 + (nt*8 + 2*t)*2) = __floats2half2_rn(s[nt][2], s[nt][3]);
      }
    }
    __syncwarp();
    {
      uint32_t psb = sb + ATT_PS + warp*4352;
      #pragma unroll
      for (int kc=0;kc<8;kc++){
        uint32_t pa[4];
        ldsm4(pa, psb + arow_l*272 + acol_l + kc*32);
        #pragma unroll
        for (int p=0;p<4;p++){
          uint32_t bf[4];
          ldsm4(bf, sb + ATT_VT + (uint32_t)(p*16 + brow_l)*272 + bcol_l + kc*32);
          mma_fp16(oa[2*p],   pa, bf[0], bf[1]);
          mma_fp16(oa[2*p+1], pa, bf[2], bf[3]);
        }
      }
    }
    __syncthreads();
  }

  l0 += __shfl_xor_sync(0xffffffffu, l0, 1);
  l0 += __shfl_xor_sync(0xffffffffu, l0, 2);
  l1 += __shfl_xor_sync(0xffffffffu, l1, 1);
  l1 += __shfl_xor_sync(0xffffffffu, l1, 2);
  float inv0 = 1.f/l0, inv1 = 1.f/l1;

  int b = bh / NHEADS, h = bh % NHEADS;
  int row0 = qt*128 + warp*16 + g;
  __half* obase = ob + (size_t)b*NSEQ*DIMM + h*HDIM;
  #pragma unroll
  for (int dt=0;dt<8;dt++){
    int col = dt*8 + 2*t;
    *(__half2*)(obase + (size_t)row0*DIMM + col)     = __floats2half2_rn(oa[dt][0]*inv0, oa[dt][1]*inv0);
    *(__half2*)(obase + (size_t)(row0+8)*DIMM + col) = __floats2half2_rn(oa[dt][2]*inv1, oa[dt][3]*inv1);
  }
}

// ---------------- host ----------------
extern "C" void kernel_launch(void* const* d_in, const int* in_sizes, int n_in,
                              void* d_out, int out_size){
  const float* x      = (const float*)d_in[0];
  const int*   cvals  = (const int*)  d_in[1];
  const float* ln1_g  = (const float*)d_in[2];
  const float* ln1_b  = (const float*)d_in[3];
  const float* kv_w   = (const float*)d_in[4];
  const float* kv_b   = (const float*)d_in[5];
  const float* sq_w   = (const float*)d_in[6];
  const float* sq_b   = (const float*)d_in[7];
  const float* cq_w   = (const float*)d_in[8];
  const float* cq_b   = (const float*)d_in[9];
  const float* proj_w = (const float*)d_in[10];
  const float* proj_b = (const float*)d_in[11];
  const float* ln2_g  = (const float*)d_in[12];
  const float* ln2_b  = (const float*)d_in[13];
  const float* fc1_w  = (const float*)d_in[14];
  const float* fc1_b  = (const float*)d_in[15];
  const float* fc2_w  = (const float*)d_in[16];
  const float* fc2_b  = (const float*)d_in[17];
  float* out = (float*)d_out;

  __half *hh, *h2, *o, *mi, *wh, *q, *k, *v;
  float *x1;
  cudaGetSymbolAddress((void**)&hh, g_hh);
  cudaGetSymbolAddress((void**)&h2, g_h2);
  cudaGetSymbolAddress((void**)&o,  g_o);
  cudaGetSymbolAddress((void**)&mi, g_mi);
  cudaGetSymbolAddress((void**)&wh, g_wh);
  cudaGetSymbolAddress((void**)&q,  g_q);
  cudaGetSymbolAddress((void**)&k,  g_k);
  cudaGetSymbolAddress((void**)&v,  g_v);
  cudaGetSymbolAddress((void**)&x1, g_x1);

  // 0. convert weights to fp16 (once per launch; deterministic)
  cvt_h<<<(1536*768/4+255)/256, 256>>>(kv_w,   wh+OFF_KV, 1536*768/4);
  cvt_h<<<( 704*768/4+255)/256, 256>>>(sq_w,   wh+OFF_SQ,  704*768/4);
  cvt_h<<<(4*64*768/4+255)/256, 256>>>(cq_w,   wh+OFF_CQ, 4*64*768/4);
  cvt_h<<<( 768*768/4+255)/256, 256>>>(proj_w, wh+OFF_PJ,  768*768/4);
  cvt_h<<<(3072*768/4+255)/256, 256>>>(fc1_w,  wh+OFF_F1, 3072*768/4);
  cvt_h<<<(768*3072/4+255)/256, 256>>>(fc2_w,  wh+OFF_F2,  768*3072/4);

  // 1. LN1 -> fp16
  ln_h<<<TOKS, 256>>>(x, ln1_g, ln1_b, hh);
  // 2. fused QKV (+ cohort routing) -> fp16 q/k/v [B*H, N, 64]
  qkv_h<<<dim3(36, 64), 128>>>(hh, wh, kv_b, sq_b, cq_b, cvals, q, k, v);
  // 3. attention (fp16 mma) -> o fp16 [B, N, 768]
  cudaFuncSetAttribute(attn_h, cudaFuncAttributeMaxDynamicSharedMemorySize, ATT_SMEM);
  attn_h<<<dim3(8, 96), 256, ATT_SMEM>>>(q, k, v, o);
  // 4. proj + residual -> x1 f32
  gemm_h<0><<<dim3(12, 64), 128>>>(o, wh+OFF_PJ, proj_b, x, x1, DIMM, DIMM);
  // 5. LN2 -> fp16
  ln_h<<<TOKS, 256>>>(x1, ln2_g, ln2_b, h2);
  // 6. fc1 + gelu -> mi fp16
  gemm_h<1><<<dim3(48, 64), 128>>>(h2, wh+OFF_F1, fc1_b, nullptr, mi, HIDM, DIMM);
  // 7. fc2 + residual -> out f32
  gemm_h<0><<<dim3(12, 64), 128>>>(mi, wh+OFF_F2, fc2_b, x1, out, DIMM, HIDM);
}

// round 15
// speedup vs baseline: 1.2546x; 1.2546x over previous
#include <cuda_runtime.h>
#include <cuda_fp16.h>
#include <cstdint>
#include <math.h>

#define TOKS 8192
#define DIMM 768
#define HIDM 3072
#define NSEQ 1024
#define NHEADS 12
#define HDIM 64
#define SCALEQ 0.125f

// ---------------- scratch ----------------
__device__ __align__(16) __half g_hh[TOKS*DIMM];       // LN1 out (fp16)
__device__ __align__(16) __half g_h2[TOKS*DIMM];       // LN2 out (fp16)
__device__ __align__(16) __half g_o [TOKS*DIMM];       // attention out (fp16)
__device__ __align__(16) __half g_mi[TOKS*HIDM];       // fc1+gelu out (fp16)
__device__ __align__(16) __half g_q [96*NSEQ*HDIM];
__device__ __align__(16) __half g_k [96*NSEQ*HDIM];
__device__ __align__(16) __half g_v [96*NSEQ*HDIM];
__device__ float  g_x1[TOKS*DIMM];
// converted fp16 weights, packed (source order)
#define OFF_KV 0
#define OFF_SQ 1179648
#define OFF_CQ 1720320
#define OFF_PJ 1916928
#define OFF_F1 2506752
#define OFF_F2 4866048
#define WH_TOTAL 7225344
__device__ __align__(16) __half g_wh[WH_TOTAL];

// ---------------- helpers ----------------
__device__ __forceinline__ uint32_t smem_u32(const void* p){
  uint32_t a; asm("{ .reg .u64 t; cvta.to.shared.u64 t, %1; cvt.u32.u64 %0, t; }" : "=r"(a) : "l"(p));
  return a;
}
__device__ __forceinline__ float gelu_exact(float x){
  return 0.5f * x * (1.0f + erff(x * 0.70710678118654752f));
}
__device__ __forceinline__ void mma_fp16(float c[4], const uint32_t a[4], uint32_t b0, uint32_t b1){
  asm volatile("mma.sync.aligned.m16n8k16.row.col.f32.f16.f16.f32 "
      "{%0,%1,%2,%3},{%4,%5,%6,%7},{%8,%9},{%0,%1,%2,%3};"
      : "+f"(c[0]), "+f"(c[1]), "+f"(c[2]), "+f"(c[3])
      : "r"(a[0]), "r"(a[1]), "r"(a[2]), "r"(a[3]), "r"(b0), "r"(b1));
}
__device__ __forceinline__ void ldsm4(uint32_t r[4], uint32_t a){
  asm volatile("ldmatrix.sync.aligned.m8n8.x4.shared.b16 {%0,%1,%2,%3}, [%4];"
    : "=r"(r[0]), "=r"(r[1]), "=r"(r[2]), "=r"(r[3]) : "r"(a));
}
__device__ __forceinline__ uint2 f4h4(float4 v){
  __half2 h01 = __float22half2_rn(make_float2(v.x, v.y));
  __half2 h23 = __float22half2_rn(make_float2(v.z, v.w));
  uint2 u;
  u.x = *(uint32_t*)&h01;
  u.y = *(uint32_t*)&h23;
  return u;
}

// smem tile: 128 rows x 40 halves (32 data + 8 pad) = 80B stride, conflict-free ldmatrix
#define HROW 40
#define HROWB 80

// ---------------- fp16 GEMM (R13-proven): 128x128 tile, 256 thr ---------------
// MODE 0: float out = acc + bias + res   MODE 1: half out = gelu(acc + bias)
template<int MODE>
__global__ __launch_bounds__(256) void gemm_h(
    const __half* __restrict__ A, const __half* __restrict__ W,
    const float* __restrict__ bias, const float* __restrict__ res,
    void* __restrict__ outv, int Nc, int K){
  __shared__ __align__(16) __half As[2][128][HROW];
  __shared__ __align__(16) __half Bs[2][128][HROW];
  int tid = threadIdx.x;
  int warp = tid>>5, lane = tid&31, g = lane>>2, t = lane&3;
  int wm = warp>>2, wn = warp&3;
  int bm = blockIdx.y*128, bn = blockIdx.x*128;

  int lr = tid>>1, lg = tid&1;
  const uint4* asrc = (const uint4*)(A + (size_t)(bm+lr)*K) + lg*2;
  const uint4* bsrc = (const uint4*)(W + (size_t)(bn+lr)*K) + lg*2;

  uint32_t sbA = smem_u32(&As[0][0][0]);
  uint32_t sbB = smem_u32(&Bs[0][0][0]);
  const uint32_t BUF = 128*HROWB;

  float acc[4][4][4];
  #pragma unroll
  for (int i=0;i<4;i++)
    #pragma unroll
    for (int j=0;j<4;j++){ acc[i][j][0]=0.f; acc[i][j][1]=0.f; acc[i][j][2]=0.f; acc[i][j][3]=0.f; }

  uint32_t a_off[4], b_off[2];
  {
    uint32_t arow_l = (uint32_t)(lane&15);
    uint32_t acol_l = (uint32_t)((lane>>4)*16);
    #pragma unroll
    for (int mt=0;mt<4;mt++)
      a_off[mt] = (uint32_t)(wm*64 + mt*16 + arow_l)*HROWB + acol_l;
    uint32_t brow_l = (uint32_t)(((lane>>4)*8) + (lane&7));
    uint32_t bcol_l = (uint32_t)((lane&8) ? 16 : 0);
    #pragma unroll
    for (int p=0;p<2;p++)
      b_off[p] = (uint32_t)(wn*32 + p*16 + brow_l)*HROWB + bcol_l;
  }

  uint4 ra0 = asrc[0], ra1 = asrc[1];
  uint4 rb0 = bsrc[0], rb1 = bsrc[1];
  {
    uint4* da = (uint4*)&As[0][lr][lg*16];
    uint4* db = (uint4*)&Bs[0][lr][lg*16];
    da[0]=ra0; da[1]=ra1; db[0]=rb0; db[1]=rb1;
  }
  __syncthreads();

  int KT = K >> 5;
  for (int kt=0; kt<KT; kt++){
    int buf = kt & 1;
    uint32_t baseA = sbA + buf*BUF;
    uint32_t baseB = sbB + buf*BUF;
    if (kt+1 < KT){
      ra0 = asrc[(kt+1)*4];   ra1 = asrc[(kt+1)*4+1];
      rb0 = bsrc[(kt+1)*4];   rb1 = bsrc[(kt+1)*4+1];
    }
    #pragma unroll
    for (int kk=0; kk<2; kk++){
      uint32_t kb = kk*32;
      uint32_t af[4][4], bf[2][4];
      #pragma unroll
      for (int mt=0;mt<4;mt++) ldsm4(af[mt], baseA + a_off[mt] + kb);
      #pragma unroll
      for (int p=0;p<2;p++)    ldsm4(bf[p],  baseB + b_off[p] + kb);
      #pragma unroll
      for (int mt=0;mt<4;mt++){
        mma_fp16(acc[mt][0], af[mt], bf[0][0], bf[0][1]);
        mma_fp16(acc[mt][1], af[mt], bf[0][2], bf[0][3]);
        mma_fp16(acc[mt][2], af[mt], bf[1][0], bf[1][1]);
        mma_fp16(acc[mt][3], af[mt], bf[1][2], bf[1][3]);
      }
    }
    if (kt+1 < KT){
      int nb = buf^1;
      uint4* da = (uint4*)&As[nb][lr][lg*16];
      uint4* db = (uint4*)&Bs[nb][lr][lg*16];
      da[0]=ra0; da[1]=ra1; db[0]=rb0; db[1]=rb1;
    }
    __syncthreads();
  }

  #pragma unroll
  for (int mt=0;mt<4;mt++){
    int row = bm + wm*64 + mt*16 + g;
    #pragma unroll
    for (int nt=0;nt<4;nt++){
      int col = bn + wn*32 + nt*8 + 2*t;
      float b0v = bias[col], b1v = bias[col+1];
      float v00 = acc[mt][nt][0] + b0v, v01 = acc[mt][nt][1] + b1v;
      float v10 = acc[mt][nt][2] + b0v, v11 = acc[mt][nt][3] + b1v;
      if (MODE==0){
        float* out = (float*)outv;
        const float* r0 = res + (size_t)row*Nc + col;
        const float* r1 = res + (size_t)(row+8)*Nc + col;
        v00 += r0[0]; v01 += r0[1]; v10 += r1[0]; v11 += r1[1];
        *(float2*)(out + (size_t)row*Nc + col)     = make_float2(v00,v01);
        *(float2*)(out + (size_t)(row+8)*Nc + col) = make_float2(v10,v11);
      } else {
        __half* out = (__half*)outv;
        v00 = gelu_exact(v00); v01 = gelu_exact(v01);
        v10 = gelu_exact(v10); v11 = gelu_exact(v11);
        *(__half2*)(out + (size_t)row*Nc + col)     = __floats2half2_rn(v00,v01);
        *(__half2*)(out + (size_t)(row+8)*Nc + col) = __floats2half2_rn(v10,v11);
      }
    }
  }
}

// ---------------- fp16 fused QKV -> fp16 q/k/v (R13-proven) --------------------
__global__ __launch_bounds__(256) void qkv_h(
    const __half* __restrict__ A, const __half* __restrict__ WH,
    const float* __restrict__ kv_b, const float* __restrict__ sq_b, const float* __restrict__ cq_b,
    const int* __restrict__ cvals,
    __half* __restrict__ qo, __half* __restrict__ ko, __half* __restrict__ vo){
  __shared__ __align__(16) __half As[2][128][HROW];
  __shared__ __align__(16) __half Bs[2][128][HROW];
  const int K = DIMM;
  int tid = threadIdx.x;
  int warp = tid>>5, lane = tid&31, g = lane>>2, t = lane&3;
  int wm = warp>>2, wn = warp&3;
  int bm = blockIdx.y*128, bn = blockIdx.x*128;
  int bb = bm >> 10;
  int coh = cvals[bb];

  int lr = tid>>1, lg = tid&1;
  const uint4* asrc = (const uint4*)(A + (size_t)(bm+lr)*K) + lg*2;
  int j = bn + lr;
  const __half* bw;
  if (j < 1536)      bw = WH + OFF_KV + (size_t)j*K;
  else if (j < 2240) bw = WH + OFF_SQ + (size_t)(j-1536)*K;
  else               bw = WH + OFF_CQ + ((size_t)coh*64 + (j-2240))*K;
  const uint4* bsrc = (const uint4*)bw + lg*2;

  uint32_t sbA = smem_u32(&As[0][0][0]);
  uint32_t sbB = smem_u32(&Bs[0][0][0]);
  const uint32_t BUF = 128*HROWB;

  float acc[4][4][4];
  #pragma unroll
  for (int i=0;i<4;i++)
    #pragma unroll
    for (int jx=0;jx<4;jx++){ acc[i][jx][0]=0.f; acc[i][jx][1]=0.f; acc[i][jx][2]=0.f; acc[i][jx][3]=0.f; }

  uint32_t a_off[4], b_off[2];
  {
    uint32_t arow_l = (uint32_t)(lane&15);
    uint32_t acol_l = (uint32_t)((lane>>4)*16);
    #pragma unroll
    for (int mt=0;mt<4;mt++)
      a_off[mt] = (uint32_t)(wm*64 + mt*16 + arow_l)*HROWB + acol_l;
    uint32_t brow_l = (uint32_t)(((lane>>4)*8) + (lane&7));
    uint32_t bcol_l = (uint32_t)((lane&8) ? 16 : 0);
    #pragma unroll
    for (int p=0;p<2;p++)
      b_off[p] = (uint32_t)(wn*32 + p*16 + brow_l)*HROWB + bcol_l;
  }

  uint4 ra0 = asrc[0], ra1 = asrc[1];
  uint4 rb0 = bsrc[0], rb1 = bsrc[1];
  {
    uint4* da = (uint4*)&As[0][lr][lg*16];
    uint4* db = (uint4*)&Bs[0][lr][lg*16];
    da[0]=ra0; da[1]=ra1; db[0]=rb0; db[1]=rb1;
  }
  __syncthreads();

  const int KT = K >> 5;  // 24
  for (int kt=0; kt<KT; kt++){
    int buf = kt & 1;
    uint32_t baseA = sbA + buf*BUF;
    uint32_t baseB = sbB + buf*BUF;
    if (kt+1 < KT){
      ra0 = asrc[(kt+1)*4];   ra1 = asrc[(kt+1)*4+1];
      rb0 = bsrc[(kt+1)*4];   rb1 = bsrc[(kt+1)*4+1];
    }
    #pragma unroll
    for (int kk=0; kk<2; kk++){
      uint32_t kb = kk*32;
      uint32_t af[4][4], bf[2][4];
      #pragma unroll
      for (int mt=0;mt<4;mt++) ldsm4(af[mt], baseA + a_off[mt] + kb);
      #pragma unroll
      for (int p=0;p<2;p++)    ldsm4(bf[p],  baseB + b_off[p] + kb);
      #pragma unroll
      for (int mt=0;mt<4;mt++){
        mma_fp16(acc[mt][0], af[mt], bf[0][0], bf[0][1]);
        mma_fp16(acc[mt][1], af[mt], bf[0][2], bf[0][3]);
        mma_fp16(acc[mt][2], af[mt], bf[1][0], bf[1][1]);
        mma_fp16(acc[mt][3], af[mt], bf[1][2], bf[1][3]);
      }
    }
    if (kt+1 < KT){
      int nb = buf^1;
      uint4* da = (uint4*)&As[nb][lr][lg*16];
      uint4* db = (uint4*)&Bs[nb][lr][lg*16];
      da[0]=ra0; da[1]=ra1; db[0]=rb0; db[1]=rb1;
    }
    __syncthreads();
  }

  #pragma unroll
  for (int mt=0;mt<4;mt++){
    int row = bm + wm*64 + mt*16 + g;
    int n = row & 1023;
    #pragma unroll
    for (int nt=0;nt<4;nt++){
      int col = bn + wn*32 + nt*8 + 2*t;
      float bias0, bias1;
      __half* dst;
      if (col < 1536){
        int part = (col >= 768) ? 1 : 0;
        int cc = col - part*768;
        int head = cc >> 6, hd = cc & 63;
        dst = (part ? vo : ko) + ((size_t)(bb*NHEADS + head)*NSEQ + n)*HDIM + hd;
        bias0 = kv_b[col]; bias1 = kv_b[col+1];
      } else if (col < 2240){
        int cc = col - 1536;
        int head = cc >> 6, hd = cc & 63;
        dst = qo + ((size_t)(bb*NHEADS + head)*NSEQ + n)*HDIM + hd;
        bias0 = sq_b[cc]; bias1 = sq_b[cc+1];
      } else {
        int hd = col - 2240;
        dst = qo + ((size_t)(bb*NHEADS + 11)*NSEQ + n)*HDIM + hd;
        bias0 = cq_b[coh*64 + hd]; bias1 = cq_b[coh*64 + hd + 1];
      }
      *(__half2*)dst = __floats2half2_rn(acc[mt][nt][0] + bias0, acc[mt][nt][1] + bias1);
      *(__half2*)(dst + 8*HDIM) = __floats2half2_rn(acc[mt][nt][2] + bias0, acc[mt][nt][3] + bias1);
    }
  }
}

// ---------------- fused f32 -> f16 conversion of all 6 weights -----------------
// region boundaries in float4 units; dst = g_wh + 4*i (packed in same order)
__global__ __launch_bounds__(256) void cvt_all(
    const float* __restrict__ s0, const float* __restrict__ s1,
    const float* __restrict__ s2, const float* __restrict__ s3,
    const float* __restrict__ s4, const float* __restrict__ s5,
    __half* __restrict__ out){
  // cumulative float4 boundaries: kv, sq, cq, pj, f1, f2
  const int c0 = 294912;            // kv  1536*768/4
  const int c1 = c0 + 135168;       // sq   704*768/4
  const int c2 = c1 + 49152;        // cq  4*64*768/4
  const int c3 = c2 + 147456;       // pj   768*768/4
  const int c4 = c3 + 589824;       // f1  3072*768/4
  const int c5 = c4 + 589824;       // f2   768*3072/4  (= WH_TOTAL/4)
  int i = blockIdx.x*256 + threadIdx.x;
  if (i >= c5) return;
  const float* src;
  int base;
  if (i < c0){ src = s0; base = 0; }
  else if (i < c1){ src = s1; base = c0; }
  else if (i < c2){ src = s2; base = c1; }
  else if (i < c3){ src = s3; base = c2; }
  else if (i < c4){ src = s4; base = c3; }
  else            { src = s5; base = c4; }
  float4 v = *(const float4*)(src + (size_t)(i - base)*4);
  *(uint2*)(out + (size_t)i*4) = f4h4(v);
}

// ---------------- LayerNorm (fp16 out) ----------------
__global__ __launch_bounds__(256) void ln_h(const float* __restrict__ x,
    const float* __restrict__ gam, const float* __restrict__ bet, __half* __restrict__ out){
  __shared__ float red[2][8];
  int row = blockIdx.x, tid = threadIdx.x;
  const float* xr = x + (size_t)row*DIMM;
  float v0 = xr[tid], v1 = xr[tid+256], v2 = xr[tid+512];
  float s = v0+v1+v2;
  float q = v0*v0 + v1*v1 + v2*v2;
  #pragma unroll
  for (int o=16;o;o>>=1){ s += __shfl_xor_sync(0xffffffffu, s, o); q += __shfl_xor_sync(0xffffffffu, q, o); }
  int wid = tid>>5, lane = tid&31;
  if (lane==0){ red[0][wid]=s; red[1][wid]=q; }
  __syncthreads();
  if (tid < 32){
    s = (lane<8)? red[0][lane] : 0.f;
    q = (lane<8)? red[1][lane] : 0.f;
    #pragma unroll
    for (int o=4;o;o>>=1){ s += __shfl_xor_sync(0xffffffffu, s, o); q += __shfl_xor_sync(0xffffffffu, q, o); }
    if (lane==0){ red[0][0]=s; red[1][0]=q; }
  }
  __syncthreads();
  float mu  = red[0][0] * (1.f/(float)DIMM);
  float var = red[1][0] * (1.f/(float)DIMM) - mu*mu;
  float rs = rsqrtf(var + 1e-5f);
  __half* orow = out + (size_t)row*DIMM;
  orow[tid]     = __float2half_rn((v0-mu)*rs*gam[tid]     + bet[tid]);
  orow[tid+256] = __float2half_rn((v1-mu)*rs*gam[tid+256] + bet[tid+256]);
  orow[tid+512] = __float2half_rn((v2-mu)*rs*gam[tid+512] + bet[tid+512]);
}

// ---------------- flash attention, fp16 mma + ldmatrix (R13-proven) ------------
#define ATT_VT 18432
#define ATT_PS 35840
#define ATT_SMEM 70656
__global__ __launch_bounds__(256, 1) void attn_h(
    const __half* __restrict__ qb, const __half* __restrict__ kb,
    const __half* __restrict__ vb, __half* __restrict__ ob){
  extern __shared__ __align__(16) char sm[];
  uint32_t sb = smem_u32(sm);
  int tid = threadIdx.x, warp = tid>>5, lane = tid&31, g = lane>>2, t = lane&3;
  int bh = blockIdx.y, qt = blockIdx.x;
  const __half* Q = qb + ((size_t)bh*NSEQ + qt*128)*HDIM;
  const __half* K = kb + (size_t)bh*NSEQ*HDIM;
  const __half* V = vb + (size_t)bh*NSEQ*HDIM;

  uint32_t arow_l = (uint32_t)(lane&15);
  uint32_t acol_l = (uint32_t)((lane>>4)*16);
  uint32_t brow_l = (uint32_t)(((lane>>4)*8) + (lane&7));
  uint32_t bcol_l = (uint32_t)((lane&8) ? 16 : 0);

  for (int i=tid; i<1024; i+=256){
    int r = i>>3, c = (i&7)*8;
    *(uint4*)(sm + r*144 + c*2) = *(const uint4*)(Q + (size_t)r*HDIM + c);
  }
  __syncthreads();
  uint32_t qa[4][4];
  #pragma unroll
  for (int kc=0;kc<4;kc++)
    ldsm4(qa[kc], sb + (uint32_t)(warp*16 + arow_l)*144 + acol_l + kc*32);
  __syncthreads();

  float m0=-1e30f, m1=-1e30f, l0=0.f, l1=0.f;
  float oa[8][4];
  #pragma unroll
  for (int dt=0;dt<8;dt++){ oa[dt][0]=0.f; oa[dt][1]=0.f; oa[dt][2]=0.f; oa[dt][3]=0.f; }

  for (int it=0; it<8; it++){
    const __half* Kt = K + (size_t)it*128*HDIM;
    const __half* Vt = V + (size_t)it*128*HDIM;
    for (int i=tid; i<1024; i+=256){
      int r = i>>3, c = (i&7)*8;
      *(uint4*)(sm + r*144 + c*2) = *(const uint4*)(Kt + (size_t)r*HDIM + c);
    }
    for (int i=tid; i<1024; i+=256){
      int key = i & 127, d8 = (i>>7)<<3;
      uint4 vv = *(const uint4*)(Vt + (size_t)key*HDIM + d8);
      const __half* hp = (const __half*)&vv;
      #pragma unroll
      for (int jj=0;jj<8;jj++)
        *(__half*)(sm + ATT_VT + (d8+jj)*272 + key*2) = hp[jj];
    }
    __syncthreads();

    float s[16][4];
    #pragma unroll
    for (int nt=0;nt<16;nt++){ s[nt][0]=0.f; s[nt][1]=0.f; s[nt][2]=0.f; s[nt][3]=0.f; }
    #pragma unroll
    for (int kc=0;kc<4;kc++){
      #pragma unroll
      for (int p=0;p<8;p++){
        uint32_t bf[4];
        ldsm4(bf, sb + (uint32_t)(p*16 + brow_l)*144 + bcol_l + kc*32);
        mma_fp16(s[2*p],   qa[kc], bf[0], bf[1]);
        mma_fp16(s[2*p+1], qa[kc], bf[2], bf[3]);
      }
    }
    #pragma unroll
    for (int nt=0;nt<16;nt++){
      s[nt][0]*=SCALEQ; s[nt][1]*=SCALEQ; s[nt][2]*=SCALEQ; s[nt][3]*=SCALEQ;
    }
    float mx0 = -1e30f, mx1 = -1e30f;
    #pragma unroll
    for (int nt=0;nt<16;nt++){
      mx0 = fmaxf(mx0, fmaxf(s[nt][0], s[nt][1]));
      mx1 = fmaxf(mx1, fmaxf(s[nt][2], s[nt][3]));
    }
    mx0 = fmaxf(mx0, __shfl_xor_sync(0xffffffffu, mx0, 1));
    mx0 = fmaxf(mx0, __shfl_xor_sync(0xffffffffu, mx0, 2));
    mx1 = fmaxf(mx1, __shfl_xor_sync(0xffffffffu, mx1, 1));
    mx1 = fmaxf(mx1, __shfl_xor_sync(0xffffffffu, mx1, 2));
    float nm0 = fmaxf(m0, mx0), nm1 = fmaxf(m1, mx1);
    float al0 = __expf(m0 - nm0), al1 = __expf(m1 - nm1);
    m0 = nm0; m1 = nm1;
    float sum0 = 0.f, sum1 = 0.f;
    #pragma unroll
    for (int nt=0;nt<16;nt++){
      s[nt][0] = __expf(s[nt][0] - m0);
      s[nt][1] = __expf(s[nt][1] - m0);
      s[nt][2] = __expf(s[nt][2] - m1);
      s[nt][3] = __expf(s[nt][3] - m1);
      sum0 += s[nt][0] + s[nt][1];
      sum1 += s[nt][2] + s[nt][3];
    }
    l0 = l0*al0 + sum0;
    l1 = l1*al1 + sum1;
    #pragma unroll
    for (int dt=0;dt<8;dt++){
      oa[dt][0]*=al0; oa[dt][1]*=al0; oa[dt][2]*=al1; oa[dt][3]*=al1;
    }
    {
      char* psw = sm + ATT_PS + warp*4352;
      #pragma unroll
      for (int nt=0;nt<16;nt++){
        *(__half2*)(psw + g*272     + (nt*8 + 2*t)*2) = __floats2half2_rn(s[nt][0], s[nt][1]);
        *(__half2*)(psw + (g+8)*272 + (nt*8 + 2*t)*2) = __floats2half2_rn(s[nt][2], s[nt][3]);
      }
    }
    __syncwarp();
    {
      uint32_t psb = sb + ATT_PS + warp*4352;
      #pragma unroll
      for (int kc=0;kc<8;kc++){
        uint32_t pa[4];
        ldsm4(pa, psb + arow_l*272 + acol_l + kc*32);
        #pragma unroll
        for (int p=0;p<4;p++){
          uint32_t bf[4];
          ldsm4(bf, sb + ATT_VT + (uint32_t)(p*16 + brow_l)*272 + bcol_l + kc*32);
          mma_fp16(oa[2*p],   pa, bf[0], bf[1]);
          mma_fp16(oa[2*p+1], pa, bf[2], bf[3]);
        }
      }
    }
    __syncthreads();
  }

  l0 += __shfl_xor_sync(0xffffffffu, l0, 1);
  l0 += __shfl_xor_sync(0xffffffffu, l0, 2);
  l1 += __shfl_xor_sync(0xffffffffu, l1, 1);
  l1 += __shfl_xor_sync(0xffffffffu, l1, 2);
  float inv0 = 1.f/l0, inv1 = 1.f/l1;

  int b = bh / NHEADS, h = bh % NHEADS;
  int row0 = qt*128 + warp*16 + g;
  __half* obase = ob + (size_t)b*NSEQ*DIMM + h*HDIM;
  #pragma unroll
  for (int dt=0;dt<8;dt++){
    int col = dt*8 + 2*t;
    *(__half2*)(obase + (size_t)row0*DIMM + col)     = __floats2half2_rn(oa[dt][0]*inv0, oa[dt][1]*inv0);
    *(__half2*)(obase + (size_t)(row0+8)*DIMM + col) = __floats2half2_rn(oa[dt][2]*inv1, oa[dt][3]*inv1);
  }
}

// ---------------- host ----------------
extern "C" void kernel_launch(void* const* d_in, const int* in_sizes, int n_in,
                              void* d_out, int out_size){
  const float* x      = (const float*)d_in[0];
  const int*   cvals  = (const int*)  d_in[1];
  const float* ln1_g  = (const float*)d_in[2];
  const float* ln1_b  = (const float*)d_in[3];
  const float* kv_w   = (const float*)d_in[4];
  const float* kv_b   = (const float*)d_in[5];
  const float* sq_w   = (const float*)d_in[6];
  const float* sq_b   = (const float*)d_in[7];
  const float* cq_w   = (const float*)d_in[8];
  const float* cq_b   = (const float*)d_in[9];
  const float* proj_w = (const float*)d_in[10];
  const float* proj_b = (const float*)d_in[11];
  const float* ln2_g  = (const float*)d_in[12];
  const float* ln2_b  = (const float*)d_in[13];
  const float* fc1_w  = (const float*)d_in[14];
  const float* fc1_b  = (const float*)d_in[15];
  const float* fc2_w  = (const float*)d_in[16];
  const float* fc2_b  = (const float*)d_in[17];
  float* out = (float*)d_out;

  __half *hh, *h2, *o, *mi, *wh, *q, *k, *v;
  float *x1;
  cudaGetSymbolAddress((void**)&hh, g_hh);
  cudaGetSymbolAddress((void**)&h2, g_h2);
  cudaGetSymbolAddress((void**)&o,  g_o);
  cudaGetSymbolAddress((void**)&mi, g_mi);
  cudaGetSymbolAddress((void**)&wh, g_wh);
  cudaGetSymbolAddress((void**)&q,  g_q);
  cudaGetSymbolAddress((void**)&k,  g_k);
  cudaGetSymbolAddress((void**)&v,  g_v);
  cudaGetSymbolAddress((void**)&x1, g_x1);

  // 0. fused weight conversion (one launch)
  cvt_all<<<(WH_TOTAL/4 + 255)/256, 256>>>(kv_w, sq_w, cq_w, proj_w, fc1_w, fc2_w, wh);
  // 1. LN1 -> fp16
  ln_h<<<TOKS, 256>>>(x, ln1_g, ln1_b, hh);
  // 2. fused QKV (+ cohort routing) -> fp16 q/k/v [B*H, N, 64]
  qkv_h<<<dim3(18, 64), 256>>>(hh, wh, kv_b, sq_b, cq_b, cvals, q, k, v);
  // 3. attention (fp16 mma) -> o fp16 [B, N, 768]
  cudaFuncSetAttribute(attn_h, cudaFuncAttributeMaxDynamicSharedMemorySize, ATT_SMEM);
  attn_h<<<dim3(8, 96), 256, ATT_SMEM>>>(q, k, v, o);
  // 4. proj + residual -> x1 f32
  gemm_h<0><<<dim3(6, 64), 256>>>(o, wh+OFF_PJ, proj_b, x, x1, DIMM, DIMM);
  // 5. LN2 -> fp16
  ln_h<<<TOKS, 256>>>(x1, ln2_g, ln2_b, h2);
  // 6. fc1 + gelu -> mi fp16
  gemm_h<1><<<dim3(24, 64), 256>>>(h2, wh+OFF_F1, fc1_b, nullptr, mi, HIDM, DIMM);
  // 7. fc2 + residual -> out f32
  gemm_h<0><<<dim3(6, 64), 256>>>(mi, wh+OFF_F2, fc2_b, x1, out, DIMM, HIDM);
}